// round 3
// baseline (speedup 1.0000x reference)
#include <cuda_runtime.h>
#include <math.h>

// Problem constants (fixed by the dataset)
#define NNODE 100000
#define NEDGE 1600000

// ---------------- scratch (device globals; no runtime allocation) ----------------
__device__ float g_h[NNODE * 128];     // projected features h = x @ W
__device__ float g_x[NNODE * 128];     // layer activations (ping buffer)
__device__ float g_asrc[NNODE * 4];    // per-node per-head src attention logits
__device__ float g_adst[NNODE * 4];    // per-node per-head dst attention logits
__device__ int   g_deg[NNODE];
__device__ int   g_rowstart[NNODE + 1];
__device__ int   g_cursor[NNODE];
__device__ int   g_csr[NEDGE + NNODE]; // src ids grouped by dst (incl. self loop)
__device__ int   g_bsum[1024];

// ---------------- CSR build ----------------
__global__ void k_zero_deg(int n) {
    int i = blockIdx.x * blockDim.x + threadIdx.x;
    if (i < n) g_deg[i] = 0;
}

__global__ void k_hist(const int* __restrict__ dst, int E) {
    int i = blockIdx.x * blockDim.x + threadIdx.x;
    if (i < E) atomicAdd(&g_deg[dst[i]], 1);
}

// block-wise inclusive scan of (deg[i] + 1)  (the +1 is the self loop)
__global__ void k_scan1(int n) {
    __shared__ int sm[1024];
    int t = threadIdx.x;
    int i = blockIdx.x * 1024 + t;
    int v = (i < n) ? (g_deg[i] + 1) : 0;
    sm[t] = v;
    __syncthreads();
#pragma unroll
    for (int off = 1; off < 1024; off <<= 1) {
        int u = (t >= off) ? sm[t - off] : 0;
        __syncthreads();
        sm[t] += u;
        __syncthreads();
    }
    if (i < n) g_rowstart[i + 1] = sm[t];
    if (t == 1023) g_bsum[blockIdx.x] = sm[t];
}

__global__ void k_scan2(int nb) {
    __shared__ int sm[1024];
    int t = threadIdx.x;
    int v = (t < nb) ? g_bsum[t] : 0;
    sm[t] = v;
    __syncthreads();
#pragma unroll
    for (int off = 1; off < 1024; off <<= 1) {
        int u = (t >= off) ? sm[t - off] : 0;
        __syncthreads();
        sm[t] += u;
        __syncthreads();
    }
    if (t < nb) g_bsum[t] = sm[t] - v;  // exclusive
}

__global__ void k_scan3(int n) {
    int t = threadIdx.x;
    int i = blockIdx.x * 1024 + t;
    if (i < n) g_rowstart[i + 1] += g_bsum[blockIdx.x];
    if (i == 0) g_rowstart[0] = 0;
}

__global__ void k_cursor(int n) {
    int i = blockIdx.x * blockDim.x + threadIdx.x;
    if (i < n) g_cursor[i] = g_rowstart[i];
}

__global__ void k_scatter(const int* __restrict__ src, const int* __restrict__ dst,
                          int E, int n) {
    int i = blockIdx.x * blockDim.x + threadIdx.x;
    if (i < E) {
        int d = dst[i];
        int p = atomicAdd(&g_cursor[d], 1);
        g_csr[p] = src[i];
    } else if (i < E + n) {
        int u = i - E;  // self loop
        int p = atomicAdd(&g_cursor[u], 1);
        g_csr[p] = u;
    }
}

// ---------------- GEMM + fused attention dots ----------------
// h[n, M] = X[n, K] @ W[K, M];  asrc[n,h] = sum_c h*As;  adst[n,h] = sum_c h*Ad
// Block: 256 threads = 8 warps, 8 rows/warp => 64 rows/block. Full W in smem.
template <int K, int M>
__global__ __launch_bounds__(256) void gemm_attn(
    const float* __restrict__ X, const float* __restrict__ W,
    const float* __restrict__ As, const float* __restrict__ Ad,
    float* __restrict__ Hout, float* __restrict__ asrc, float* __restrict__ adst,
    int n)
{
    constexpr int RPW = 8;
    constexpr int ROWS = 64;
    constexpr int XV = K / 4;
    extern __shared__ float sm[];
    float* Wsh = sm;            // K*M floats
    float* Xsh = sm + K * M;    // ROWS*K floats

    int tid = threadIdx.x, lane = tid & 31, wid = tid >> 5;
    int base = blockIdx.x * ROWS;

    for (int i = tid; i < (K * M) / 4; i += 256)
        ((float4*)Wsh)[i] = ((const float4*)W)[i];

    for (int i = tid; i < ROWS * XV; i += 256) {
        int r = i / XV, c = i % XV;
        int gr = base + r;
        float4 v = (gr < n) ? ((const float4*)X)[gr * XV + c]
                            : make_float4(0.f, 0.f, 0.f, 0.f);
        ((float4*)Xsh)[i] = v;
    }
    __syncthreads();

    int rb = wid * RPW;

    if constexpr (M == 128) {
        float4 acc[RPW];
#pragma unroll
        for (int r = 0; r < RPW; r++) acc[r] = make_float4(0.f, 0.f, 0.f, 0.f);

#pragma unroll 2
        for (int kb = 0; kb < K; kb += 4) {
            float4 w0 = ((float4*)Wsh)[(kb + 0) * 32 + lane];
            float4 w1 = ((float4*)Wsh)[(kb + 1) * 32 + lane];
            float4 w2 = ((float4*)Wsh)[(kb + 2) * 32 + lane];
            float4 w3 = ((float4*)Wsh)[(kb + 3) * 32 + lane];
#pragma unroll
            for (int r = 0; r < RPW; r++) {
                float4 xv = ((float4*)Xsh)[(rb + r) * XV + (kb >> 2)];
                acc[r].x += xv.x * w0.x + xv.y * w1.x + xv.z * w2.x + xv.w * w3.x;
                acc[r].y += xv.x * w0.y + xv.y * w1.y + xv.z * w2.y + xv.w * w3.y;
                acc[r].z += xv.x * w0.z + xv.y * w1.z + xv.z * w2.z + xv.w * w3.z;
                acc[r].w += xv.x * w0.w + xv.y * w1.w + xv.z * w2.w + xv.w * w3.w;
            }
        }

        float4 asv = ((const float4*)As)[lane];
        float4 adv = ((const float4*)Ad)[lane];
        int head = lane >> 3;
#pragma unroll
        for (int r = 0; r < RPW; r++) {
            int gr = base + rb + r;
            if (gr < n) {
                ((float4*)Hout)[gr * 32 + lane] = acc[r];
                float ps = acc[r].x * asv.x + acc[r].y * asv.y +
                           acc[r].z * asv.z + acc[r].w * asv.w;
                float pd = acc[r].x * adv.x + acc[r].y * adv.y +
                           acc[r].z * adv.z + acc[r].w * adv.w;
#pragma unroll
                for (int o = 4; o; o >>= 1) {
                    ps += __shfl_xor_sync(0xffffffffu, ps, o);
                    pd += __shfl_xor_sync(0xffffffffu, pd, o);
                }
                if ((lane & 7) == 0) {
                    asrc[gr * 4 + head] = ps;
                    adst[gr * 4 + head] = pd;
                }
            }
        }
    } else {  // M == 32, single head
        float acc[RPW];
#pragma unroll
        for (int r = 0; r < RPW; r++) acc[r] = 0.f;

#pragma unroll 2
        for (int kb = 0; kb < K; kb += 4) {
            float w0 = Wsh[(kb + 0) * 32 + lane];
            float w1 = Wsh[(kb + 1) * 32 + lane];
            float w2 = Wsh[(kb + 2) * 32 + lane];
            float w3 = Wsh[(kb + 3) * 32 + lane];
#pragma unroll
            for (int r = 0; r < RPW; r++) {
                float4 xv = ((float4*)Xsh)[(rb + r) * XV + (kb >> 2)];
                acc[r] += xv.x * w0 + xv.y * w1 + xv.z * w2 + xv.w * w3;
            }
        }

        float asv = As[lane], adv = Ad[lane];
#pragma unroll
        for (int r = 0; r < RPW; r++) {
            int gr = base + rb + r;
            if (gr < n) {
                Hout[gr * 32 + lane] = acc[r];
                float ps = acc[r] * asv, pd = acc[r] * adv;
#pragma unroll
                for (int o = 16; o; o >>= 1) {
                    ps += __shfl_xor_sync(0xffffffffu, ps, o);
                    pd += __shfl_xor_sync(0xffffffffu, pd, o);
                }
                if (lane == 0) { asrc[gr] = ps; adst[gr] = pd; }
            }
        }
    }
}

// ---------------- per-dst-node online-softmax aggregation, fused bias+LN+ELU ----
// one warp per node; lane owns 4 channels (head = lane>>3)
__global__ __launch_bounds__(256) void agg_ln_elu(
    const float* __restrict__ Hin,
    const float* __restrict__ bias, const float* __restrict__ gamma,
    const float* __restrict__ beta, float* __restrict__ Xout, int n)
{
    int w = (blockIdx.x * blockDim.x + threadIdx.x) >> 5;
    if (w >= n) return;
    int lane = threadIdx.x & 31, head = lane >> 3;
    int r0 = g_rowstart[w], r1 = g_rowstart[w + 1];
    float adv = g_adst[w * 4 + head];
    const float4* H4 = (const float4*)Hin;

    float m = -INFINITY, dnm = 0.f;
    float ax = 0.f, ay = 0.f, az = 0.f, aw = 0.f;

    int s = g_csr[r0];
    float4 hv = H4[s * 32 + lane];
    float ar = g_asrc[s * 4 + head];

    for (int j = r0; j < r1; ++j) {
        int jn = j + 1;
        int sn = (jn < r1) ? g_csr[jn] : s;
        float4 hn = H4[sn * 32 + lane];          // prefetch next edge's row
        float an = g_asrc[sn * 4 + head];

        float e = ar + adv;
        e = fmaxf(e, 0.2f * e);                  // leaky_relu, slope 0.2
        float mn = fmaxf(m, e);
        float sc = __expf(m - mn);               // 1 if m stays max, else rescale
        float p  = __expf(e - mn);
        m = mn;
        dnm = dnm * sc + p;
        ax = ax * sc + p * hv.x;
        ay = ay * sc + p * hv.y;
        az = az * sc + p * hv.z;
        aw = aw * sc + p * hv.w;

        hv = hn; ar = an; s = sn;
    }

    float inv = 1.f / (dnm + 1e-16f);
    float4 b4 = ((const float4*)bias)[lane];
    float ox = ax * inv + b4.x, oy = ay * inv + b4.y;
    float oz = az * inv + b4.z, ow = aw * inv + b4.w;

    // LayerNorm over 128 channels via warp reduction
    float ssum = ox + oy + oz + ow;
#pragma unroll
    for (int o = 16; o; o >>= 1) ssum += __shfl_xor_sync(0xffffffffu, ssum, o);
    float mu = ssum * (1.f / 128.f);
    float dx = ox - mu, dy = oy - mu, dz = oz - mu, dw = ow - mu;
    float vs = dx * dx + dy * dy + dz * dz + dw * dw;
#pragma unroll
    for (int o = 16; o; o >>= 1) vs += __shfl_xor_sync(0xffffffffu, vs, o);
    float rstd = rsqrtf(vs * (1.f / 128.f) + 1e-5f);

    float4 g4 = ((const float4*)gamma)[lane];
    float4 be4 = ((const float4*)beta)[lane];
    float yx = g4.x * dx * rstd + be4.x;
    float yy = g4.y * dy * rstd + be4.y;
    float yz = g4.z * dz * rstd + be4.z;
    float yw = g4.w * dw * rstd + be4.w;
    yx = yx > 0.f ? yx : expm1f(yx);             // ELU
    yy = yy > 0.f ? yy : expm1f(yy);
    yz = yz > 0.f ? yz : expm1f(yz);
    yw = yw > 0.f ? yw : expm1f(yw);

    ((float4*)Xout)[w * 32 + lane] = make_float4(yx, yy, yz, yw);
}

// final layer: 1 head, 32 channels, no LN/ELU, output = agg + bias
__global__ __launch_bounds__(256) void agg_final(
    const float* __restrict__ Hin, const float* __restrict__ bias,
    float* __restrict__ Out, int n)
{
    int w = (blockIdx.x * blockDim.x + threadIdx.x) >> 5;
    if (w >= n) return;
    int lane = threadIdx.x & 31;
    int r0 = g_rowstart[w], r1 = g_rowstart[w + 1];
    float adv = g_adst[w];

    float m = -INFINITY, dnm = 0.f, acc = 0.f;
    int s = g_csr[r0];
    float hv = Hin[s * 32 + lane];
    float ar = g_asrc[s];

    for (int j = r0; j < r1; ++j) {
        int jn = j + 1;
        int sn = (jn < r1) ? g_csr[jn] : s;
        float hn = Hin[sn * 32 + lane];
        float an = g_asrc[sn];

        float e = ar + adv;
        e = fmaxf(e, 0.2f * e);
        float mn = fmaxf(m, e);
        float sc = __expf(m - mn);
        float p  = __expf(e - mn);
        m = mn;
        dnm = dnm * sc + p;
        acc = acc * sc + p * hv;

        hv = hn; ar = an; s = sn;
    }
    Out[w * 32 + lane] = acc / (dnm + 1e-16f) + bias[lane];
}

// ---------------- orchestration ----------------
extern "C" void kernel_launch(void* const* d_in, const int* in_sizes, int n_in,
                              void* d_out, int out_size)
{
    const float* x   = (const float*)d_in[0];
    const int*   ei  = (const int*)d_in[1];
    int N = in_sizes[0] / 64;
    int E = in_sizes[1] / 2;

    const float* W0  = (const float*)d_in[2];
    const float* as0 = (const float*)d_in[3];
    const float* ad0 = (const float*)d_in[4];
    const float* b0  = (const float*)d_in[5];
    const float* gm0 = (const float*)d_in[6];
    const float* be0 = (const float*)d_in[7];
    const float* W1  = (const float*)d_in[8];
    const float* as1 = (const float*)d_in[9];
    const float* ad1 = (const float*)d_in[10];
    const float* b1  = (const float*)d_in[11];
    const float* gm1 = (const float*)d_in[12];
    const float* be1 = (const float*)d_in[13];
    const float* W2  = (const float*)d_in[14];
    const float* as2 = (const float*)d_in[15];
    const float* ad2 = (const float*)d_in[16];
    const float* b2  = (const float*)d_in[17];
    const float* gm2 = (const float*)d_in[18];
    const float* be2 = (const float*)d_in[19];
    const float* Wf  = (const float*)d_in[20];
    const float* asf = (const float*)d_in[21];
    const float* adf = (const float*)d_in[22];
    const float* bf  = (const float*)d_in[23];
    float* out = (float*)d_out;

    float *gh, *gx, *gas, *gad;
    cudaGetSymbolAddress((void**)&gh,  g_h);
    cudaGetSymbolAddress((void**)&gx,  g_x);
    cudaGetSymbolAddress((void**)&gas, g_asrc);
    cudaGetSymbolAddress((void**)&gad, g_adst);

    size_t sm0 = (size_t)(64 * 128 + 64 * 64) * 4;    // 48 KB
    size_t sm1 = (size_t)(128 * 128 + 64 * 128) * 4;  // 96 KB
    size_t smf = (size_t)(128 * 32 + 64 * 128) * 4;   // 48 KB
    cudaFuncSetAttribute(gemm_attn<64, 128>,
                         cudaFuncAttributeMaxDynamicSharedMemorySize, (int)sm0);
    cudaFuncSetAttribute(gemm_attn<128, 128>,
                         cudaFuncAttributeMaxDynamicSharedMemorySize, (int)sm1);
    cudaFuncSetAttribute(gemm_attn<128, 32>,
                         cudaFuncAttributeMaxDynamicSharedMemorySize, (int)smf);

    // ---- CSR build (dst-grouped, self loops appended) ----
    k_zero_deg<<<(N + 255) / 256, 256>>>(N);
    k_hist<<<(E + 255) / 256, 256>>>(ei + E, E);
    int NB = (N + 1023) / 1024;
    k_scan1<<<NB, 1024>>>(N);
    k_scan2<<<1, 1024>>>(NB);
    k_scan3<<<NB, 1024>>>(N);
    k_cursor<<<(N + 255) / 256, 256>>>(N);
    k_scatter<<<(E + N + 255) / 256, 256>>>(ei, ei + E, E, N);

    int gb = (N + 63) / 64;
    int ab = (N + 7) / 8;

    // ---- layer 0 ----
    gemm_attn<64, 128><<<gb, 256, sm0>>>(x, W0, as0, ad0, gh, gas, gad, N);
    agg_ln_elu<<<ab, 256>>>(gh, b0, gm0, be0, gx, N);
    // ---- layer 1 ----
    gemm_attn<128, 128><<<gb, 256, sm1>>>(gx, W1, as1, ad1, gh, gas, gad, N);
    agg_ln_elu<<<ab, 256>>>(gh, b1, gm1, be1, gx, N);
    // ---- layer 2 ----
    gemm_attn<128, 128><<<gb, 256, sm1>>>(gx, W2, as2, ad2, gh, gas, gad, N);
    agg_ln_elu<<<ab, 256>>>(gh, b2, gm2, be2, gx, N);
    // ---- final layer ----
    gemm_attn<128, 32><<<gb, 256, smf>>>(gx, Wf, asf, adf, gh, gas, gad, N);
    agg_final<<<ab, 256>>>(gh, bf, out, N);
}

// round 5
// speedup vs baseline: 1.0827x; 1.0827x over previous
#include <cuda_runtime.h>
#include <math.h>

// Problem constants (fixed by the dataset)
#define NNODE 100000
#define NEDGE 1600000

typedef unsigned long long ull;

// ---------------- scratch (device globals; no runtime allocation) ----------------
__device__ float g_h[NNODE * 128];     // projected features h = x @ W
__device__ float g_x[NNODE * 128];     // layer activations (ping buffer)
__device__ float g_asrc[NNODE * 4];    // per-node per-head src attention logits
__device__ float g_adst[NNODE * 4];    // per-node per-head dst attention logits
__device__ float g_Wt[128 * 128];      // transposed weights [M][K]
__device__ int   g_deg[NNODE];
__device__ int   g_rowstart[NNODE + 1];
__device__ int   g_cursor[NNODE];
__device__ int   g_csr[NEDGE + NNODE]; // src ids grouped by dst (incl. self loop)
__device__ int   g_bsum[1024];

// ---------------- f32x2 packed helpers (sm_103a) ----------------
__device__ __forceinline__ ull ffma2(ull a, ull b, ull c) {
    ull d;
    asm("fma.rn.f32x2 %0, %1, %2, %3;" : "=l"(d) : "l"(a), "l"(b), "l"(c));
    return d;
}
__device__ __forceinline__ ull addf2(ull a, ull b) {
    ull d;
    asm("add.rn.f32x2 %0, %1, %2;" : "=l"(d) : "l"(a), "l"(b));
    return d;
}
__device__ __forceinline__ ull packf2(float lo, float hi) {
    ull d;
    asm("mov.b64 %0, {%1, %2};" : "=l"(d) : "f"(lo), "f"(hi));
    return d;
}
__device__ __forceinline__ void unpackf2(ull v, float& lo, float& hi) {
    asm("mov.b64 {%0, %1}, %2;" : "=f"(lo), "=f"(hi) : "l"(v));
}

// ---------------- CSR build ----------------
__global__ void k_zero_deg(int n) {
    int i = blockIdx.x * blockDim.x + threadIdx.x;
    if (i < n) g_deg[i] = 0;
}

__global__ void k_hist(const int* __restrict__ dst, int E) {
    int i = blockIdx.x * blockDim.x + threadIdx.x;
    if (i < E) atomicAdd(&g_deg[dst[i]], 1);
}

// block-wise inclusive scan of (deg[i] + 1)  (the +1 is the self loop)
__global__ void k_scan1(int n) {
    __shared__ int sm[1024];
    int t = threadIdx.x;
    int i = blockIdx.x * 1024 + t;
    int v = (i < n) ? (g_deg[i] + 1) : 0;
    sm[t] = v;
    __syncthreads();
#pragma unroll
    for (int off = 1; off < 1024; off <<= 1) {
        int u = (t >= off) ? sm[t - off] : 0;
        __syncthreads();
        sm[t] += u;
        __syncthreads();
    }
    if (i < n) g_rowstart[i + 1] = sm[t];
    if (t == 1023) g_bsum[blockIdx.x] = sm[t];
}

__global__ void k_scan2(int nb) {
    __shared__ int sm[1024];
    int t = threadIdx.x;
    int v = (t < nb) ? g_bsum[t] : 0;
    sm[t] = v;
    __syncthreads();
#pragma unroll
    for (int off = 1; off < 1024; off <<= 1) {
        int u = (t >= off) ? sm[t - off] : 0;
        __syncthreads();
        sm[t] += u;
        __syncthreads();
    }
    if (t < nb) g_bsum[t] = sm[t] - v;  // exclusive
}

__global__ void k_scan3(int n) {
    int t = threadIdx.x;
    int i = blockIdx.x * 1024 + t;
    if (i < n) g_rowstart[i + 1] += g_bsum[blockIdx.x];
    if (i == 0) g_rowstart[0] = 0;
}

__global__ void k_cursor(int n) {
    int i = blockIdx.x * blockDim.x + threadIdx.x;
    if (i < n) g_cursor[i] = g_rowstart[i];
}

__global__ void k_scatter(const int* __restrict__ src, const int* __restrict__ dst,
                          int E, int n) {
    int i = blockIdx.x * blockDim.x + threadIdx.x;
    if (i < E) {
        int d = dst[i];
        int p = atomicAdd(&g_cursor[d], 1);
        g_csr[p] = src[i];
    } else if (i < E + n) {
        int u = i - E;  // self loop
        int p = atomicAdd(&g_cursor[u], 1);
        g_csr[p] = u;
    }
}

// ---------------- weight transpose: Wt[m][k] = W[k][m] ----------------
__global__ void k_transpose(const float* __restrict__ W, int K, int M) {
    int i = blockIdx.x * blockDim.x + threadIdx.x;
    if (i < K * M) {
        int k = i / M, m = i % M;      // coalesced read
        g_Wt[m * K + k] = W[i];
    }
}

// ---------------- GEMM (f32x2) + fused attention dots ----------------
// h[n, M] = X[n, K] @ W[K, M] using packed fp32x2 FMA, pairing over k.
// W pre-transposed to g_Wt[M][K]; smem copy padded to LDW=K+4 (conflict-free
// LDS.128: lane stride = 4 banks -> disjoint quad coverage per phase).
// Lane owns columns {lane + 32u}; for M=128 that is channel `lane` of head u,
// so attention dots are clean per-head 32-lane packed butterflies.
// Block: 256 threads = 8 warps, 8 rows/warp => 64 rows/block.
template <int K, int CPL>   // CPL = cols per lane (4 -> M=128, 1 -> M=32)
__global__ __launch_bounds__(256) void gemm_attn(
    const float* __restrict__ X,
    const float* __restrict__ As, const float* __restrict__ Ad,
    float* __restrict__ Hout, float* __restrict__ asrc, float* __restrict__ adst,
    int n)
{
    constexpr int M = 32 * CPL;
    constexpr int RPW = 8;
    constexpr int ROWS = 64;
    constexpr int LDW = K + 4;
    extern __shared__ float sm[];
    float* Wsh = sm;                 // M * LDW floats, [m][k] padded
    float* Xsh = sm + M * LDW;       // ROWS * K floats, row-major

    int tid = threadIdx.x, lane = tid & 31, wid = tid >> 5;
    int base = blockIdx.x * ROWS;

    // stage transposed W: g_Wt[m][k] -> Wsh[m*LDW + k]  (float4, conflict-free)
    for (int i = tid; i < (M * K) / 4; i += 256) {
        int m = i / (K / 4), kq = i % (K / 4);
        ((float4*)(Wsh + m * LDW))[kq] =
            ((const float4*)g_Wt)[i];
    }
    // stage X rows
    for (int i = tid; i < ROWS * (K / 4); i += 256) {
        int r = i / (K / 4), c = i % (K / 4);
        int gr = base + r;
        float4 v = (gr < n) ? ((const float4*)X)[gr * (K / 4) + c]
                            : make_float4(0.f, 0.f, 0.f, 0.f);
        ((float4*)Xsh)[i] = v;
    }
    __syncthreads();

    int rb = wid * RPW;

    // accumulators: (even-k partial, odd-k partial) packed pairs
    ull acc[RPW][CPL];
#pragma unroll
    for (int r = 0; r < RPW; r++)
#pragma unroll
        for (int u = 0; u < CPL; u++) acc[r][u] = 0ull;

#pragma unroll 2
    for (int kb = 0; kb < K; kb += 4) {
        ulonglong2 wq[CPL];
#pragma unroll
        for (int u = 0; u < CPL; u++)
            wq[u] = *(const ulonglong2*)(Wsh + (lane + 32 * u) * LDW + kb);
#pragma unroll
        for (int r = 0; r < RPW; r++) {
            ulonglong2 xq = *(const ulonglong2*)(Xsh + (rb + r) * K + kb);
#pragma unroll
            for (int u = 0; u < CPL; u++) {
                acc[r][u] = ffma2(xq.x, wq[u].x, acc[r][u]);
                acc[r][u] = ffma2(xq.y, wq[u].y, acc[r][u]);
            }
        }
    }

    // epilogue: finalize, store h, attention dots via packed butterflies
    if constexpr (CPL == 4) {
        float asv[4], adv[4];
#pragma unroll
        for (int u = 0; u < 4; u++) {
            asv[u] = As[u * 32 + lane];   // As[h][c], c = lane
            adv[u] = Ad[u * 32 + lane];
        }
#pragma unroll
        for (int r = 0; r < RPW; r++) {
            int gr = base + rb + r;
            if (gr < n) {
                float v[4];
#pragma unroll
                for (int u = 0; u < 4; u++) {
                    float lo, hi; unpackf2(acc[r][u], lo, hi);
                    v[u] = lo + hi;
                    Hout[gr * 128 + lane + 32 * u] = v[u];
                }
                ull p01 = packf2(v[0] * asv[0], v[1] * asv[1]);
                ull p23 = packf2(v[2] * asv[2], v[3] * asv[3]);
                ull q01 = packf2(v[0] * adv[0], v[1] * adv[1]);
                ull q23 = packf2(v[2] * adv[2], v[3] * adv[3]);
#pragma unroll
                for (int o = 16; o; o >>= 1) {
                    p01 = addf2(p01, __shfl_xor_sync(0xffffffffu, p01, o));
                    p23 = addf2(p23, __shfl_xor_sync(0xffffffffu, p23, o));
                    q01 = addf2(q01, __shfl_xor_sync(0xffffffffu, q01, o));
                    q23 = addf2(q23, __shfl_xor_sync(0xffffffffu, q23, o));
                }
                if (lane == 0) {
                    float a, b;
                    unpackf2(p01, a, b); asrc[gr * 4 + 0] = a; asrc[gr * 4 + 1] = b;
                    unpackf2(p23, a, b); asrc[gr * 4 + 2] = a; asrc[gr * 4 + 3] = b;
                    unpackf2(q01, a, b); adst[gr * 4 + 0] = a; adst[gr * 4 + 1] = b;
                    unpackf2(q23, a, b); adst[gr * 4 + 2] = a; adst[gr * 4 + 3] = b;
                }
            }
        }
    } else {  // M == 32, single head
        float asv = As[lane], adv = Ad[lane];
#pragma unroll
        for (int r = 0; r < RPW; r++) {
            int gr = base + rb + r;
            if (gr < n) {
                float lo, hi; unpackf2(acc[r][0], lo, hi);
                float v = lo + hi;
                Hout[gr * 32 + lane] = v;
                ull pq = packf2(v * asv, v * adv);
#pragma unroll
                for (int o = 16; o; o >>= 1)
                    pq = addf2(pq, __shfl_xor_sync(0xffffffffu, pq, o));
                if (lane == 0) {
                    float a, b; unpackf2(pq, a, b);
                    asrc[gr] = a; adst[gr] = b;
                }
            }
        }
    }
}

// ---------------- per-dst-node online-softmax aggregation, fused bias+LN+ELU ----
// one warp per node; lane owns 4 channels (head = lane>>3).
// csr index prefetched 2 ahead so the h-row prefetch never chases a fresh index.
__global__ __launch_bounds__(256) void agg_ln_elu(
    const float* __restrict__ Hin,
    const float* __restrict__ bias, const float* __restrict__ gamma,
    const float* __restrict__ beta, float* __restrict__ Xout, int n)
{
    int w = (blockIdx.x * blockDim.x + threadIdx.x) >> 5;
    if (w >= n) return;
    int lane = threadIdx.x & 31, head = lane >> 3;
    int r0 = g_rowstart[w];
    int len = g_rowstart[w + 1] - r0;    // >= 1 (self loop)
    float adv = g_adst[w * 4 + head];
    const float4* H4 = (const float4*)Hin;

    float m = -INFINITY, dnm = 0.f;
    float ax = 0.f, ay = 0.f, az = 0.f, aw = 0.f;

    int s0 = g_csr[r0];
    int s1 = (len > 1) ? g_csr[r0 + 1] : s0;
    float4 hv = H4[s0 * 32 + lane];
    float ar = g_asrc[s0 * 4 + head];

    for (int j = 0; j < len; ++j) {
        int s2 = (j + 2 < len) ? g_csr[r0 + j + 2] : s1;  // index 2 ahead
        float4 hn = H4[s1 * 32 + lane];                   // row 1 ahead
        float an = g_asrc[s1 * 4 + head];

        float e = ar + adv;
        e = fmaxf(e, 0.2f * e);                  // leaky_relu, slope 0.2
        float mn = fmaxf(m, e);
        float sc = __expf(m - mn);               // 1 if m stays max, else rescale
        float p  = __expf(e - mn);
        m = mn;
        dnm = dnm * sc + p;
        ax = ax * sc + p * hv.x;
        ay = ay * sc + p * hv.y;
        az = az * sc + p * hv.z;
        aw = aw * sc + p * hv.w;

        hv = hn; ar = an; s1 = s2;
    }

    float inv = 1.f / (dnm + 1e-16f);
    float4 b4 = ((const float4*)bias)[lane];
    float ox = ax * inv + b4.x, oy = ay * inv + b4.y;
    float oz = az * inv + b4.z, ow = aw * inv + b4.w;

    // LayerNorm over 128 channels via warp reduction
    float ssum = ox + oy + oz + ow;
#pragma unroll
    for (int o = 16; o; o >>= 1) ssum += __shfl_xor_sync(0xffffffffu, ssum, o);
    float mu = ssum * (1.f / 128.f);
    float dx = ox - mu, dy = oy - mu, dz = oz - mu, dw = ow - mu;
    float vs = dx * dx + dy * dy + dz * dz + dw * dw;
#pragma unroll
    for (int o = 16; o; o >>= 1) vs += __shfl_xor_sync(0xffffffffu, vs, o);
    float rstd = rsqrtf(vs * (1.f / 128.f) + 1e-5f);

    float4 g4 = ((const float4*)gamma)[lane];
    float4 be4 = ((const float4*)beta)[lane];
    float yx = g4.x * dx * rstd + be4.x;
    float yy = g4.y * dy * rstd + be4.y;
    float yz = g4.z * dz * rstd + be4.z;
    float yw = g4.w * dw * rstd + be4.w;
    yx = yx > 0.f ? yx : expm1f(yx);             // ELU
    yy = yy > 0.f ? yy : expm1f(yy);
    yz = yz > 0.f ? yz : expm1f(yz);
    yw = yw > 0.f ? yw : expm1f(yw);

    ((float4*)Xout)[w * 32 + lane] = make_float4(yx, yy, yz, yw);
}

// final layer: 1 head, 32 channels, no LN/ELU, output = agg + bias
__global__ __launch_bounds__(256) void agg_final(
    const float* __restrict__ Hin, const float* __restrict__ bias,
    float* __restrict__ Out, int n)
{
    int w = (blockIdx.x * blockDim.x + threadIdx.x) >> 5;
    if (w >= n) return;
    int lane = threadIdx.x & 31;
    int r0 = g_rowstart[w];
    int len = g_rowstart[w + 1] - r0;
    float adv = g_adst[w];

    float m = -INFINITY, dnm = 0.f, acc = 0.f;
    int s0 = g_csr[r0];
    int s1 = (len > 1) ? g_csr[r0 + 1] : s0;
    float hv = Hin[s0 * 32 + lane];
    float ar = g_asrc[s0];

    for (int j = 0; j < len; ++j) {
        int s2 = (j + 2 < len) ? g_csr[r0 + j + 2] : s1;
        float hn = Hin[s1 * 32 + lane];
        float an = g_asrc[s1];

        float e = ar + adv;
        e = fmaxf(e, 0.2f * e);
        float mn = fmaxf(m, e);
        float sc = __expf(m - mn);
        float p  = __expf(e - mn);
        m = mn;
        dnm = dnm * sc + p;
        acc = acc * sc + p * hv;

        hv = hn; ar = an; s1 = s2;
    }
    Out[w * 32 + lane] = acc / (dnm + 1e-16f) + bias[lane];
}

// ---------------- orchestration ----------------
extern "C" void kernel_launch(void* const* d_in, const int* in_sizes, int n_in,
                              void* d_out, int out_size)
{
    const float* x   = (const float*)d_in[0];
    const int*   ei  = (const int*)d_in[1];
    int N = in_sizes[0] / 64;
    int E = in_sizes[1] / 2;

    const float* W0  = (const float*)d_in[2];
    const float* as0 = (const float*)d_in[3];
    const float* ad0 = (const float*)d_in[4];
    const float* b0  = (const float*)d_in[5];
    const float* gm0 = (const float*)d_in[6];
    const float* be0 = (const float*)d_in[7];
    const float* W1  = (const float*)d_in[8];
    const float* as1 = (const float*)d_in[9];
    const float* ad1 = (const float*)d_in[10];
    const float* b1  = (const float*)d_in[11];
    const float* gm1 = (const float*)d_in[12];
    const float* be1 = (const float*)d_in[13];
    const float* W2  = (const float*)d_in[14];
    const float* as2 = (const float*)d_in[15];
    const float* ad2 = (const float*)d_in[16];
    const float* b2  = (const float*)d_in[17];
    const float* gm2 = (const float*)d_in[18];
    const float* be2 = (const float*)d_in[19];
    const float* Wf  = (const float*)d_in[20];
    const float* asf = (const float*)d_in[21];
    const float* adf = (const float*)d_in[22];
    const float* bf  = (const float*)d_in[23];
    float* out = (float*)d_out;

    float *gh, *gx, *gas, *gad;
    cudaGetSymbolAddress((void**)&gh,  g_h);
    cudaGetSymbolAddress((void**)&gx,  g_x);
    cudaGetSymbolAddress((void**)&gas, g_asrc);
    cudaGetSymbolAddress((void**)&gad, g_adst);

    // smem sizes: M*(K+4) + 64*K floats
    size_t sm0 = (size_t)(128 * 68  + 64 * 64)  * 4;  // K=64,  M=128: 51200
    size_t sm1 = (size_t)(128 * 132 + 64 * 128) * 4;  // K=128, M=128: 100352
    size_t smf = (size_t)(32  * 132 + 64 * 128) * 4;  // K=128, M=32 : 49664
    cudaFuncSetAttribute(gemm_attn<64, 4>,
                         cudaFuncAttributeMaxDynamicSharedMemorySize, (int)sm0);
    cudaFuncSetAttribute(gemm_attn<128, 4>,
                         cudaFuncAttributeMaxDynamicSharedMemorySize, (int)sm1);
    cudaFuncSetAttribute(gemm_attn<128, 1>,
                         cudaFuncAttributeMaxDynamicSharedMemorySize, (int)smf);

    // ---- CSR build (dst-grouped, self loops appended) ----
    k_zero_deg<<<(N + 255) / 256, 256>>>(N);
    k_hist<<<(E + 255) / 256, 256>>>(ei + E, E);
    int NB = (N + 1023) / 1024;
    k_scan1<<<NB, 1024>>>(N);
    k_scan2<<<1, 1024>>>(NB);
    k_scan3<<<NB, 1024>>>(N);
    k_cursor<<<(N + 255) / 256, 256>>>(N);
    k_scatter<<<(E + N + 255) / 256, 256>>>(ei, ei + E, E, N);

    int gb = (N + 63) / 64;
    int ab = (N + 7) / 8;

    // ---- layer 0 ----
    k_transpose<<<(64 * 128 + 255) / 256, 256>>>(W0, 64, 128);
    gemm_attn<64, 4><<<gb, 256, sm0>>>(x, as0, ad0, gh, gas, gad, N);
    agg_ln_elu<<<ab, 256>>>(gh, b0, gm0, be0, gx, N);
    // ---- layer 1 ----
    k_transpose<<<(128 * 128 + 255) / 256, 256>>>(W1, 128, 128);
    gemm_attn<128, 4><<<gb, 256, sm1>>>(gx, as1, ad1, gh, gas, gad, N);
    agg_ln_elu<<<ab, 256>>>(gh, b1, gm1, be1, gx, N);
    // ---- layer 2 ----
    k_transpose<<<(128 * 128 + 255) / 256, 256>>>(W2, 128, 128);
    gemm_attn<128, 4><<<gb, 256, sm1>>>(gx, as2, ad2, gh, gas, gad, N);
    agg_ln_elu<<<ab, 256>>>(gh, b2, gm2, be2, gx, N);
    // ---- final layer ----
    k_transpose<<<(128 * 32 + 255) / 256, 256>>>(Wf, 128, 32);
    gemm_attn<128, 1><<<gb, 256, smf>>>(gx, asf, adf, gh, gas, gad, N);
    agg_final<<<ab, 256>>>(gh, bf, out, N);
}